// round 3
// baseline (speedup 1.0000x reference)
#include <cuda_runtime.h>
#include <cuda_bf16.h>
#include <stdint.h>

#define EPSQ 1e-5f
#define MTOK 32768
#define DDIM 1024
#define FDIM 3072

// ---------------- scratch (__device__ globals; no allocation) ----------------
__device__ int8_t g_qx[(size_t)MTOK * DDIM];        // 32 MB
__device__ int8_t g_qh[(size_t)MTOK * FDIM];        // 96 MB
__device__ int8_t g_w1[(size_t)FDIM * DDIM];        // 3 MB
__device__ int8_t g_w2[(size_t)DDIM * FDIM];        // 3 MB
__device__ float  g_hidden[(size_t)MTOK * FDIM];    // 384 MB
__device__ float  g_ascale[MTOK];
__device__ float  g_hscale[MTOK];
__device__ float  g_wpart[2048];
__device__ float  g_wmeta[4];  // ws1, fac1, ws2, fac2

// ---------------- ptx helpers (base sm_80+ ISA only) ----------------
__device__ __forceinline__ uint32_t s2u(const void* p) {
    uint32_t a;
    asm("{ .reg .u64 t; cvta.to.shared.u64 t, %1; cvt.u32.u64 %0, t; }" : "=r"(a) : "l"(p));
    return a;
}
__device__ __forceinline__ void cp16(uint32_t saddr, const void* gaddr) {
    asm volatile("cp.async.cg.shared.global [%0], [%1], 16;" :: "r"(saddr), "l"(gaddr) : "memory");
}
__device__ __forceinline__ void ldm_x4(uint32_t* r, uint32_t addr) {
    asm volatile("ldmatrix.sync.aligned.m8n8.x4.shared.b16 {%0,%1,%2,%3}, [%4];"
                 : "=r"(r[0]), "=r"(r[1]), "=r"(r[2]), "=r"(r[3]) : "r"(addr));
}
__device__ __forceinline__ void imma(int* d, const uint32_t* a, const uint32_t* b) {
    asm volatile(
        "mma.sync.aligned.m16n8k32.row.col.s32.s8.s8.s32 "
        "{%0,%1,%2,%3}, {%4,%5,%6,%7}, {%8,%9}, {%0,%1,%2,%3};"
        : "+r"(d[0]), "+r"(d[1]), "+r"(d[2]), "+r"(d[3])
        : "r"(a[0]), "r"(a[1]), "r"(a[2]), "r"(a[3]), "r"(b[0]), "r"(b[1]));
}

// ---------------- weight quantization ----------------
// Deterministic partial sums of |w| over flat views: blocks 0..1023 -> up_w,
// 1024..2047 -> down_w (each block: 3072 contiguous floats).
__global__ void k_wsum(const float* __restrict__ up_w, const float* __restrict__ down_w) {
    int b = blockIdx.x, t = threadIdx.x;
    const float* base = (b < 1024) ? (up_w + (size_t)b * 3072)
                                   : (down_w + (size_t)(b - 1024) * 3072);
    const float4* v4 = (const float4*)base;
    float s = 0.f;
#pragma unroll
    for (int j = 0; j < 3; j++) {
        float4 v = v4[t + j * 256];
        s += fabsf(v.x) + fabsf(v.y) + fabsf(v.z) + fabsf(v.w);
    }
    for (int o = 16; o > 0; o >>= 1) s += __shfl_down_sync(0xffffffffu, s, o);
    __shared__ float red[8];
    if ((t & 31) == 0) red[t >> 5] = s;
    __syncthreads();
    if (t == 0) {
        float tot = 0.f;
        for (int i = 0; i < 8; i++) tot += red[i];
        g_wpart[b] = tot;
    }
}

__global__ void k_wscale() {
    int t = threadIdx.x;  // 1024 threads
    __shared__ float s1[1024], s2[1024];
    s1[t] = g_wpart[t];
    s2[t] = g_wpart[1024 + t];
    __syncthreads();
    for (int o = 512; o > 0; o >>= 1) {
        if (t < o) { s1[t] += s1[t + o]; s2[t] += s2[t + o]; }
        __syncthreads();
    }
    if (t == 0) {
        float m1 = s1[0] / (3072.0f * 1024.0f);
        float m2 = s2[0] / (3072.0f * 1024.0f);
        float f1 = fmaxf(m1, EPSQ), f2 = fmaxf(m2, EPSQ);
        g_wmeta[0] = 1.0f / f1; g_wmeta[1] = f1;
        g_wmeta[2] = 1.0f / f2; g_wmeta[3] = f2;
    }
}

__global__ void k_ternarize(const float* __restrict__ up_w, const float* __restrict__ down_w) {
    const size_t half = (size_t)3072 * 1024;
    size_t i = ((size_t)blockIdx.x * 256 + threadIdx.x) * 4;
    const float* src;
    int8_t* dst;
    float ws;
    if (i < half) { src = up_w + i;            dst = g_w1 + i;          ws = g_wmeta[0]; }
    else          { src = down_w + (i - half); dst = g_w2 + (i - half); ws = g_wmeta[2]; }
    float4 w = *(const float4*)src;
    char4 q;
    q.x = (signed char)fminf(fmaxf(rintf(w.x * ws), -1.f), 1.f);
    q.y = (signed char)fminf(fmaxf(rintf(w.y * ws), -1.f), 1.f);
    q.z = (signed char)fminf(fmaxf(rintf(w.z * ws), -1.f), 1.f);
    q.w = (signed char)fminf(fmaxf(rintf(w.w * ws), -1.f), 1.f);
    *(char4*)dst = q;
}

// ---------------- activation quantization ----------------
__global__ void k_quant_x(const float* __restrict__ x) {
    int m = blockIdx.x, t = threadIdx.x;  // 256 threads, row of 1024
    const float4* row = (const float4*)(x + (size_t)m * DDIM);
    float4 v = row[t];
    float am = fmaxf(fmaxf(fabsf(v.x), fabsf(v.y)), fmaxf(fabsf(v.z), fabsf(v.w)));
    for (int o = 16; o > 0; o >>= 1) am = fmaxf(am, __shfl_xor_sync(0xffffffffu, am, o));
    __shared__ float red[8];
    __shared__ float s_c;
    if ((t & 31) == 0) red[t >> 5] = am;
    __syncthreads();
    if (t == 0) {
        float c = red[0];
        for (int i = 1; i < 8; i++) c = fmaxf(c, red[i]);
        c = fmaxf(c, EPSQ);
        s_c = c;
        g_ascale[m] = c / 127.0f;
    }
    __syncthreads();
    float scale = 127.0f / s_c;
    char4 q;
    q.x = (signed char)fminf(fmaxf(rintf(v.x * scale), -128.f), 127.f);
    q.y = (signed char)fminf(fmaxf(rintf(v.y * scale), -128.f), 127.f);
    q.z = (signed char)fminf(fmaxf(rintf(v.z * scale), -128.f), 127.f);
    q.w = (signed char)fminf(fmaxf(rintf(v.w * scale), -128.f), 127.f);
    *(char4*)(g_qx + (size_t)m * DDIM + t * 4) = q;
}

__global__ void k_quant_h() {
    int m = blockIdx.x, t = threadIdx.x;  // 256 threads, row of 3072
    const float4* row = (const float4*)(g_hidden + (size_t)m * FDIM);
    float4 v[3];
    float am = 0.f;
#pragma unroll
    for (int j = 0; j < 3; j++) {
        v[j] = row[t + j * 256];
        am = fmaxf(am, fmaxf(fmaxf(fabsf(v[j].x), fabsf(v[j].y)),
                             fmaxf(fabsf(v[j].z), fabsf(v[j].w))));
    }
    for (int o = 16; o > 0; o >>= 1) am = fmaxf(am, __shfl_xor_sync(0xffffffffu, am, o));
    __shared__ float red[8];
    __shared__ float s_c;
    if ((t & 31) == 0) red[t >> 5] = am;
    __syncthreads();
    if (t == 0) {
        float c = red[0];
        for (int i = 1; i < 8; i++) c = fmaxf(c, red[i]);
        c = fmaxf(c, EPSQ);
        s_c = c;
        g_hscale[m] = c / 127.0f;
    }
    __syncthreads();
    float scale = 127.0f / s_c;
#pragma unroll
    for (int j = 0; j < 3; j++) {
        char4 q;
        q.x = (signed char)fminf(fmaxf(rintf(v[j].x * scale), -128.f), 127.f);
        q.y = (signed char)fminf(fmaxf(rintf(v[j].y * scale), -128.f), 127.f);
        q.z = (signed char)fminf(fmaxf(rintf(v[j].z * scale), -128.f), 127.f);
        q.w = (signed char)fminf(fmaxf(rintf(v[j].w * scale), -128.f), 127.f);
        *(char4*)(g_qh + (size_t)m * FDIM + (t + j * 256) * 4) = q;
    }
}

// ---------------- int8 tensor-core GEMM (mma.sync m16n8k32), 128x128 tile ----------------
// 256 threads = 8 warps in 2(m) x 4(n); warp tile 64x32. K-step 64 bytes,
// double-buffered cp.async. Smem rows of 64B, chunk swizzle c ^= (r>>1)&3
// (conflict-free for both the stores and ldmatrix reads).
__global__ void __launch_bounds__(256, 1)
k_gemm(const float* __restrict__ bias, float* __restrict__ out2,
       int N, int K, int KT, int NT, int mode)
{
    __shared__ int8_t smem[2][16384];  // per buf: A[128][64] then B[128][64]
    const uint32_t sbase = s2u(smem);
    int tid = threadIdx.x, wid = tid >> 5, lane = tid & 31;
    int mt = blockIdx.x / NT, nt = blockIdx.x % NT;
    int m0 = mt * 128, n0 = nt * 128;
    int wm = (wid >> 2) * 64, wn = (wid & 3) * 32;

    const int8_t* A = (mode == 1) ? g_qx : g_qh;
    const int8_t* B = (mode == 1) ? g_w1 : g_w2;

    const int chr = tid >> 2;   // load row (0..63)
    const int chc = tid & 3;    // 16B chunk (0..3)

    int d[4][4][4];
#pragma unroll
    for (int mi = 0; mi < 4; mi++)
#pragma unroll
        for (int ni = 0; ni < 4; ni++)
#pragma unroll
            for (int e = 0; e < 4; e++) d[mi][ni][e] = 0;

#define LOAD_TILE(kt, buf) do {                                                  \
    int _k0 = (kt) * 64;                                                         \
    uint32_t _b = sbase + (uint32_t)(buf) * 16384u;                              \
    _Pragma("unroll")                                                            \
    for (int _j = 0; _j < 2; _j++) {                                             \
        int _r = chr + _j * 64;                                                  \
        uint32_t _so = (uint32_t)(_r * 64 + ((chc ^ ((_r >> 1) & 3)) << 4));     \
        cp16(_b + _so,         A + (size_t)(m0 + _r) * K + _k0 + chc * 16);      \
        cp16(_b + 8192u + _so, B + (size_t)(n0 + _r) * K + _k0 + chc * 16);      \
    }                                                                            \
    asm volatile("cp.async.commit_group;" ::: "memory");                         \
} while (0)

    LOAD_TILE(0, 0);

    for (int kt = 0; kt < KT; kt++) {
        if (kt + 1 < KT) {
            LOAD_TILE(kt + 1, (kt + 1) & 1);
            asm volatile("cp.async.wait_group 1;" ::: "memory");
        } else {
            asm volatile("cp.async.wait_group 0;" ::: "memory");
        }
        __syncthreads();

        uint32_t ab = sbase + (uint32_t)(kt & 1) * 16384u;
        uint32_t bb = ab + 8192u;
#pragma unroll
        for (int kc = 0; kc < 2; kc++) {
            uint32_t afr[4][4], bfr[2][4];
#pragma unroll
            for (int mi = 0; mi < 4; mi++) {
                int row = wm + mi * 16 + (lane & 7) + ((lane >> 3) & 1) * 8;
                int chunk = 2 * kc + (lane >> 4);
                ldm_x4(afr[mi], ab + (uint32_t)(row * 64 + ((chunk ^ ((row >> 1) & 3)) << 4)));
            }
#pragma unroll
            for (int np = 0; np < 2; np++) {
                int n = wn + np * 16 + ((lane >> 4) << 3) + (lane & 7);
                int chunk = 2 * kc + ((lane >> 3) & 1);
                ldm_x4(bfr[np], bb + (uint32_t)(n * 64 + ((chunk ^ ((n >> 1) & 3)) << 4)));
            }
#pragma unroll
            for (int mi = 0; mi < 4; mi++)
#pragma unroll
                for (int ni = 0; ni < 4; ni++)
                    imma(d[mi][ni], afr[mi], bfr[ni >> 1] + (ni & 1) * 2);
        }
        __syncthreads();
    }

    // ---------------- epilogue ----------------
    const float wf = g_wmeta[(mode == 1) ? 1 : 3];
    const float* sc = (mode == 1) ? g_ascale : g_hscale;
    float* outp = (mode == 1) ? g_hidden : out2;

#pragma unroll
    for (int mi = 0; mi < 4; mi++) {
        int mlo = m0 + wm + mi * 16 + (lane >> 2);
        float slo = sc[mlo] * wf;
        float shi = sc[mlo + 8] * wf;
        float* rlo = outp + (size_t)mlo * N;
        float* rhi = outp + (size_t)(mlo + 8) * N;
#pragma unroll
        for (int ni = 0; ni < 4; ni++) {
            int n = n0 + wn + ni * 8 + 2 * (lane & 3);
            float2 bv = *(const float2*)(bias + n);
            float2 v0, v1;
            v0.x = (float)d[mi][ni][0] * slo + bv.x;
            v0.y = (float)d[mi][ni][1] * slo + bv.y;
            v1.x = (float)d[mi][ni][2] * shi + bv.x;
            v1.y = (float)d[mi][ni][3] * shi + bv.y;
            if (mode == 1) {
                v0.x = fmaxf(v0.x, 0.f); v0.x *= v0.x;
                v0.y = fmaxf(v0.y, 0.f); v0.y *= v0.y;
                v1.x = fmaxf(v1.x, 0.f); v1.x *= v1.x;
                v1.y = fmaxf(v1.y, 0.f); v1.y *= v1.y;
            }
            *(float2*)(rlo + n) = v0;
            *(float2*)(rhi + n) = v1;
        }
    }
}

// ---------------- launch ----------------
extern "C" void kernel_launch(void* const* d_in, const int* in_sizes, int n_in,
                              void* d_out, int out_size) {
    (void)in_sizes; (void)n_in; (void)out_size;
    const float* x      = (const float*)d_in[0];
    const float* up_w   = (const float*)d_in[1];
    const float* up_b   = (const float*)d_in[2];
    const float* down_w = (const float*)d_in[3];
    const float* down_b = (const float*)d_in[4];
    float* out = (float*)d_out;

    k_wsum<<<2048, 256>>>(up_w, down_w);
    k_wscale<<<1, 1024>>>();
    k_ternarize<<<6144, 256>>>(up_w, down_w);
    k_quant_x<<<MTOK, 256>>>(x);
    // GEMM1: M=32768, N=3072, K=1024 -> relu^2 into g_hidden
    k_gemm<<<256 * 24, 256>>>(up_b, nullptr, FDIM, DDIM, DDIM / 64, 24, 1);
    k_quant_h<<<MTOK, 256>>>();
    // GEMM2: M=32768, N=1024, K=3072 -> out with bias
    k_gemm<<<256 * 8, 256>>>(down_b, out, DDIM, FDIM, FDIM / 64, 8, 2);
}